// round 11
// baseline (speedup 1.0000x reference)
#include <cuda_runtime.h>
#include <stdint.h>

#define NOBJ 1024
#define DF   512
#define DBF  64
#define EN   32768
#define HF   1024

// ---------------- scratch (static __device__, no allocs) ----------------
__device__ float g_Psub[NOBJ * HF];              // 4 MB
__device__ float g_Pobj[NOBJ * HF];              // 4 MB
__device__ float g_bbG[(size_t)EN * DBF];        // 8 MB  gathered bb rows
__device__ float g_H[(size_t)EN * HF];           // 128 MB hidden
__device__ float g_OUT[(size_t)EN * DF];         // 64 MB  per-edge out
__device__ int   g_sub[EN], g_obj[EN];
__device__ int   g_cnt[NOBJ], g_cur[NOBJ];
__device__ int   g_off[NOBJ + 1];
__device__ int   g_elist[EN];
__device__ int   g_is64;                         // pairs dtype flag

// ---------------- dtype sniff: int64 pairs have zero high words ----------
__global__ void k_detect(const int* __restrict__ p32) {
    if (threadIdx.x == 0 && blockIdx.x == 0) {
        int any = 0;
#pragma unroll
        for (int i = 0; i < 32; i++) any |= p32[2 * i + 1];
        // int64 LE: words 1,3,5,... are high halves of values in [0,1024) -> 0.
        // int32: words 1,3,5,... are obj indices; all-zero is ~impossible.
        g_is64 = (any == 0) ? 1 : 0;
    }
}

// ---------------- small prep kernels ----------------
__global__ void k_zero() {
    int i = blockIdx.x * blockDim.x + threadIdx.x;
    if (i < NOBJ) { g_cnt[i] = 0; g_cur[i] = 0; }
}

__global__ void k_prep(const void* __restrict__ pairs) {
    int e = blockIdx.x * blockDim.x + threadIdx.x;
    if (e < EN) {
        int s, o;
        if (g_is64) {
            const long long* p = (const long long*)pairs;
            s = (int)p[2 * e]; o = (int)p[2 * e + 1];
        } else {
            const int* p = (const int*)pairs;
            s = p[2 * e]; o = p[2 * e + 1];
        }
        g_sub[e] = s; g_obj[e] = o;
        atomicAdd(&g_cnt[s], 1);
    }
}

// gather bb rows using already-decoded indices (dtype-independent)
__global__ void k_gather(const float* __restrict__ bb) {
    size_t idx = (size_t)blockIdx.x * blockDim.x + threadIdx.x;
    if (idx < (size_t)EN * DBF) {
        int e = (int)(idx >> 6);
        int k = (int)(idx & 63);
        size_t s = (size_t)g_sub[e], o = (size_t)g_obj[e];
        g_bbG[idx] = bb[(s * NOBJ + o) * DBF + k];
    }
}

// ---------------- fp32 tiled GEMM, double-buffered smem ----------------
// C[M,Nc] = A[M,K](lda) @ B[K,Nc](ldb), row-major all.
// relu_mode==1: C = relu(acc + Psub[sub[m]] + Pobj[obj[m]] + b1)   (h-GEMM)
// relu_mode==0: C = acc                                            (plain)
#define BM 128
#define BN 128
#define BK 16
__global__ __launch_bounds__(256)
void k_sgemm(int M, int Nc, int K,
             const float* __restrict__ A, int lda,
             const float* __restrict__ B, int ldb,
             float* __restrict__ C, int ldc,
             const float* __restrict__ bias, int relu_mode) {
    __shared__ float As[2][BK][BM];
    __shared__ float Bs[2][BK][BN];
    int tid = threadIdx.x;
    int tx = tid & 15, ty = tid >> 4;
    int m0 = blockIdx.x * BM, n0 = blockIdx.y * BN;

    // per-thread load coordinates (2 float4 each for A and B per tile)
    int aid0 = tid * 2,     arow0 = aid0 >> 2, ac0 = (aid0 & 3) * 4;
    int aid1 = tid * 2 + 1, arow1 = aid1 >> 2, ac1 = (aid1 & 3) * 4;
    int bid0 = tid * 2,     brow0 = bid0 >> 5, bc0 = (bid0 & 31) * 4;
    int bid1 = tid * 2 + 1, brow1 = bid1 >> 5, bc1 = (bid1 & 31) * 4;

    float acc[8][8];
#pragma unroll
    for (int i = 0; i < 8; i++)
#pragma unroll
        for (int j = 0; j < 8; j++) acc[i][j] = 0.f;

    float4 ra0, ra1, rb0, rb1;

    // prologue: fetch tile 0 and store into buffer 0
    ra0 = *(const float4*)(A + (size_t)(m0 + arow0) * lda + ac0);
    ra1 = *(const float4*)(A + (size_t)(m0 + arow1) * lda + ac1);
    rb0 = *(const float4*)(B + (size_t)brow0 * ldb + n0 + bc0);
    rb1 = *(const float4*)(B + (size_t)brow1 * ldb + n0 + bc1);
    As[0][ac0 + 0][arow0] = ra0.x; As[0][ac0 + 1][arow0] = ra0.y;
    As[0][ac0 + 2][arow0] = ra0.z; As[0][ac0 + 3][arow0] = ra0.w;
    As[0][ac1 + 0][arow1] = ra1.x; As[0][ac1 + 1][arow1] = ra1.y;
    As[0][ac1 + 2][arow1] = ra1.z; As[0][ac1 + 3][arow1] = ra1.w;
    *(float4*)(&Bs[0][brow0][bc0]) = rb0;
    *(float4*)(&Bs[0][brow1][bc1]) = rb1;
    __syncthreads();

    int buf = 0;
    for (int k0 = 0; k0 < K; k0 += BK) {
        int kn = k0 + BK;
        bool has_next = kn < K;
        if (has_next) {
            ra0 = *(const float4*)(A + (size_t)(m0 + arow0) * lda + kn + ac0);
            ra1 = *(const float4*)(A + (size_t)(m0 + arow1) * lda + kn + ac1);
            rb0 = *(const float4*)(B + (size_t)(kn + brow0) * ldb + n0 + bc0);
            rb1 = *(const float4*)(B + (size_t)(kn + brow1) * ldb + n0 + bc1);
        }
#pragma unroll
        for (int k = 0; k < BK; k++) {
            float a[8], b[8];
            *(float4*)(a)     = *(float4*)(&As[buf][k][ty * 8]);
            *(float4*)(a + 4) = *(float4*)(&As[buf][k][ty * 8 + 4]);
            *(float4*)(b)     = *(float4*)(&Bs[buf][k][tx * 8]);
            *(float4*)(b + 4) = *(float4*)(&Bs[buf][k][tx * 8 + 4]);
#pragma unroll
            for (int i = 0; i < 8; i++)
#pragma unroll
                for (int j = 0; j < 8; j++) acc[i][j] += a[i] * b[j];
        }
        if (has_next) {
            int nb = buf ^ 1;
            As[nb][ac0 + 0][arow0] = ra0.x; As[nb][ac0 + 1][arow0] = ra0.y;
            As[nb][ac0 + 2][arow0] = ra0.z; As[nb][ac0 + 3][arow0] = ra0.w;
            As[nb][ac1 + 0][arow1] = ra1.x; As[nb][ac1 + 1][arow1] = ra1.y;
            As[nb][ac1 + 2][arow1] = ra1.z; As[nb][ac1 + 3][arow1] = ra1.w;
            *(float4*)(&Bs[nb][brow0][bc0]) = rb0;
            *(float4*)(&Bs[nb][brow1][bc1]) = rb1;
        }
        __syncthreads();
        buf ^= 1;
    }

    if (relu_mode == 0) {
#pragma unroll
        for (int i = 0; i < 8; i++) {
            int m = m0 + ty * 8 + i;
            float* cp = C + (size_t)m * ldc + n0 + tx * 8;
            *(float4*)cp       = make_float4(acc[i][0], acc[i][1], acc[i][2], acc[i][3]);
            *(float4*)(cp + 4) = make_float4(acc[i][4], acc[i][5], acc[i][6], acc[i][7]);
        }
    } else {
#pragma unroll
        for (int i = 0; i < 8; i++) {
            int m = m0 + ty * 8 + i;
            int s = g_sub[m], o = g_obj[m];
            const float* ps = g_Psub + (size_t)s * HF + n0 + tx * 8;
            const float* po = g_Pobj + (size_t)o * HF + n0 + tx * 8;
            const float* bp = bias + n0 + tx * 8;
            float r[8];
#pragma unroll
            for (int j = 0; j < 8; j++) {
                float v = acc[i][j] + ps[j] + po[j] + bp[j];
                r[j] = v > 0.f ? v : 0.f;
            }
            float* cp = C + (size_t)m * ldc + n0 + tx * 8;
            *(float4*)cp       = make_float4(r[0], r[1], r[2], r[3]);
            *(float4*)(cp + 4) = make_float4(r[4], r[5], r[6], r[7]);
        }
    }
}

// ---------------- deterministic CSR ----------------
__global__ void k_scan() {
    __shared__ int sh[NOBJ];
    int t = threadIdx.x;
    sh[t] = g_cnt[t];
    __syncthreads();
    for (int d = 1; d < NOBJ; d <<= 1) {
        int v = (t >= d) ? sh[t - d] : 0;
        __syncthreads();
        sh[t] += v;
        __syncthreads();
    }
    g_off[t + 1] = sh[t];
    if (t == 0) g_off[0] = 0;
}

__global__ void k_scatter() {
    int e = blockIdx.x * blockDim.x + threadIdx.x;
    if (e < EN) {
        int s = g_sub[e];
        int pos = g_off[s] + atomicAdd(&g_cur[s], 1);
        g_elist[pos] = e;
    }
}

// sort each bucket ascending -> fully deterministic summation order
__global__ void k_sort() {
    int n = blockIdx.x * blockDim.x + threadIdx.x;
    if (n < NOBJ) {
        int b = g_off[n], e2 = g_off[n + 1];
        for (int i = b + 1; i < e2; i++) {
            int v = g_elist[i];
            int j = i - 1;
            while (j >= b && g_elist[j] > v) { g_elist[j + 1] = g_elist[j]; j--; }
            g_elist[j + 1] = v;
        }
    }
}

// new_feats[n] = (OF[n] + sum_e OUT[e] + cnt*b2) / (1 + cnt)
__global__ void k_final(const float* __restrict__ of,
                        const float* __restrict__ b2,
                        float* __restrict__ out) {
    int n = blockIdx.x;
    int t = threadIdx.x;  // 128
    int b = g_off[n], e2 = g_off[n + 1];
    float a0 = 0, a1 = 0, a2 = 0, a3 = 0;
    for (int j = b; j < e2; j++) {
        const float* r = g_OUT + (size_t)g_elist[j] * DF;
        a0 += r[t];       a1 += r[t + 128];
        a2 += r[t + 256]; a3 += r[t + 384];
    }
    float cnt = (float)(e2 - b);
    float inv = 1.f / (1.f + cnt);
    const float* ofr = of + (size_t)n * DF;
    float* orow = out + (size_t)n * DF;
    orow[t]       = (ofr[t]       + a0 + cnt * b2[t])       * inv;
    orow[t + 128] = (ofr[t + 128] + a1 + cnt * b2[t + 128]) * inv;
    orow[t + 256] = (ofr[t + 256] + a2 + cnt * b2[t + 256]) * inv;
    orow[t + 384] = (ofr[t + 384] + a3 + cnt * b2[t + 384]) * inv;
}

__global__ void k_pairs_f(const void* __restrict__ pairs, float* __restrict__ out) {
    int i = blockIdx.x * blockDim.x + threadIdx.x;
    if (i < EN * 2) {
        long long v = g_is64 ? ((const long long*)pairs)[i]
                             : (long long)((const int*)pairs)[i];
        out[i] = (float)v;
    }
}

// ---------------- launch ----------------
extern "C" void kernel_launch(void* const* d_in, const int* in_sizes, int n_in,
                              void* d_out, int out_size) {
    const float* of    = (const float*)d_in[0];
    const float* bb    = (const float*)d_in[1];
    const void*  pairs = d_in[2];
    const float* W1    = (const float*)d_in[3];
    const float* b1    = (const float*)d_in[4];
    const float* W2    = (const float*)d_in[5];
    const float* b2    = (const float*)d_in[6];
    float* out = (float*)d_out;
    cudaStream_t s = 0;

    float *pPsub, *pPobj, *pBbG, *pH, *pOUT;
    cudaGetSymbolAddress((void**)&pPsub, g_Psub);
    cudaGetSymbolAddress((void**)&pPobj, g_Pobj);
    cudaGetSymbolAddress((void**)&pBbG,  g_bbG);
    cudaGetSymbolAddress((void**)&pH,    g_H);
    cudaGetSymbolAddress((void**)&pOUT,  g_OUT);

    k_detect<<<1, 32, 0, s>>>((const int*)pairs);
    k_zero<<<(NOBJ + 255) / 256, 256, 0, s>>>();
    k_prep<<<EN / 256, 256, 0, s>>>(pairs);
    k_gather<<<(EN * DBF) / 256, 256, 0, s>>>(bb);

    // Psub = OF @ W1[0:512,:]   Pobj = OF @ W1[512:1024,:]
    k_sgemm<<<dim3(NOBJ / BM, HF / BN), 256, 0, s>>>(
        NOBJ, HF, DF, of, DF, W1, HF, pPsub, HF, nullptr, 0);
    k_sgemm<<<dim3(NOBJ / BM, HF / BN), 256, 0, s>>>(
        NOBJ, HF, DF, of, DF, W1 + (size_t)512 * HF, HF, pPobj, HF, nullptr, 0);

    // H = relu(bbG @ W1[1024:1088,:] + Psub[sub] + Pobj[obj] + b1)
    k_sgemm<<<dim3(EN / BM, HF / BN), 256, 0, s>>>(
        EN, HF, DBF, pBbG, DBF, W1 + (size_t)1024 * HF, HF, pH, HF, b1, 1);

    // OUT = H @ W2
    k_sgemm<<<dim3(EN / BM, DF / BN), 256, 0, s>>>(
        EN, DF, HF, pH, HF, W2, DF, pOUT, DF, nullptr, 0);

    // deterministic segment sum
    k_scan<<<1, NOBJ, 0, s>>>();
    k_scatter<<<EN / 256, 256, 0, s>>>();
    k_sort<<<(NOBJ + 255) / 256, 256, 0, s>>>();
    k_final<<<NOBJ, 128, 0, s>>>(of, b2, out);

    // output assembly: new_feats | bboxes_embedding | pairs (layout per out_size)
    const long long NEWF = (long long)NOBJ * DF;             // 524288
    const long long BBn  = (long long)NOBJ * NOBJ * DBF;     // 67108864
    long long osz = (long long)out_size;
    if (osz >= NEWF + BBn) {
        cudaMemcpyAsync(out + NEWF, bb, (size_t)BBn * sizeof(float),
                        cudaMemcpyDeviceToDevice, s);
        long long rem = osz - NEWF - BBn;
        if (rem == (long long)EN * 2) {
            // pairs as float (or int32 raw would also be 2E words — convert,
            // since __output__ dtype is float32)
            k_pairs_f<<<(EN * 2) / 256, 256, 0, s>>>(pairs, out + NEWF + BBn);
        } else if (rem == (long long)EN * 4) {
            // pairs raw int64 bytes occupying rem float slots
            cudaMemcpyAsync(out + NEWF + BBn, pairs,
                            (size_t)EN * 2 * sizeof(long long),
                            cudaMemcpyDeviceToDevice, s);
        }
    }
    // osz == NEWF: only new_feats is compared — nothing further to write.
}

// round 14
// speedup vs baseline: 1.1533x; 1.1533x over previous
#include <cuda_runtime.h>
#include <cuda_bf16.h>
#include <stdint.h>

#define NOBJ 1024
#define DF   512
#define DBF  64
#define EN   32768
#define HF   1024
#define W1R  (DF + DF + DBF)   // 1088

// ---------------- scratch (static __device__, no allocs) ----------------
__device__ float g_Psub[NOBJ * HF];                         // fp32, exact adds in epilogue
__device__ float g_Pobj[NOBJ * HF];
__device__ __align__(16) __nv_bfloat16 g_OFh[NOBJ * DF];
__device__ __align__(16) __nv_bfloat16 g_OFl[NOBJ * DF];
__device__ __align__(16) __nv_bfloat16 g_W1h[W1R * HF];
__device__ __align__(16) __nv_bfloat16 g_W1l[W1R * HF];
__device__ __align__(16) __nv_bfloat16 g_W2h[HF * DF];
__device__ __align__(16) __nv_bfloat16 g_W2l[HF * DF];
__device__ __align__(16) __nv_bfloat16 g_bbGh[(size_t)EN * DBF];
__device__ __align__(16) __nv_bfloat16 g_bbGl[(size_t)EN * DBF];
__device__ __align__(16) __nv_bfloat16 g_Hh[(size_t)EN * HF];
__device__ __align__(16) __nv_bfloat16 g_Hl[(size_t)EN * HF];
__device__ float g_OUT[(size_t)EN * DF];
__device__ int   g_sub[EN], g_obj[EN];
__device__ int   g_cnt[NOBJ], g_cur[NOBJ];
__device__ int   g_off[NOBJ + 1];
__device__ int   g_elist[EN];
__device__ int   g_is64;

// ---------------- dtype sniff ----------------
__global__ void k_detect(const int* __restrict__ p32) {
    if (threadIdx.x == 0 && blockIdx.x == 0) {
        int any = 0;
#pragma unroll
        for (int i = 0; i < 32; i++) any |= p32[2 * i + 1];
        g_is64 = (any == 0) ? 1 : 0;
    }
}

__global__ void k_zero() {
    int i = blockIdx.x * blockDim.x + threadIdx.x;
    if (i < NOBJ) { g_cnt[i] = 0; g_cur[i] = 0; }
}

__global__ void k_prep(const void* __restrict__ pairs) {
    int e = blockIdx.x * blockDim.x + threadIdx.x;
    if (e < EN) {
        int s, o;
        if (g_is64) {
            const long long* p = (const long long*)pairs;
            s = (int)p[2 * e]; o = (int)p[2 * e + 1];
        } else {
            const int* p = (const int*)pairs;
            s = p[2 * e]; o = p[2 * e + 1];
        }
        g_sub[e] = s; g_obj[e] = o;
        atomicAdd(&g_cnt[s], 1);
    }
}

// fp32 -> (bf16 hi, bf16 lo) split
__global__ void k_split(const float* __restrict__ src,
                        __nv_bfloat16* __restrict__ hi,
                        __nv_bfloat16* __restrict__ lo, int n) {
    int i = blockIdx.x * blockDim.x + threadIdx.x;
    if (i < n) {
        float v = src[i];
        __nv_bfloat16 h = __float2bfloat16(v);
        hi[i] = h;
        lo[i] = __float2bfloat16(v - __bfloat162float(h));
    }
}

// gather bb rows, splitting to bf16 hi/lo on the fly
__global__ void k_gather(const float* __restrict__ bb) {
    size_t idx = (size_t)blockIdx.x * blockDim.x + threadIdx.x;
    if (idx < (size_t)EN * DBF) {
        int e = (int)(idx >> 6);
        int k = (int)(idx & 63);
        size_t s = (size_t)g_sub[e], o = (size_t)g_obj[e];
        float v = bb[(s * NOBJ + o) * DBF + k];
        __nv_bfloat16 h = __float2bfloat16(v);
        g_bbGh[idx] = h;
        g_bbGl[idx] = __float2bfloat16(v - __bfloat162float(h));
    }
}

// ---------------- split-bf16 tensor-core GEMM ----------------
// C[M,N] = A[M,K] @ B[K,N], A/B given as (hi,lo) bf16 row-major.
// 3-MMA split: D += Ahi*Bhi + Ahi*Blo + Alo*Bhi (fp32 accum; bf16 products exact).
// mode 0: write fp32 C.  mode 1: relu(acc + Psub[sub]+Pobj[obj]+bias) -> (Chi,Clo) bf16.
#define BM 128
#define BN 128
#define BK 32
#define APAD 36
#define BPAD 36

__device__ __forceinline__ void mma16816(float* c, const uint32_t* a, const uint32_t* b) {
    asm volatile(
        "mma.sync.aligned.m16n8k16.row.col.f32.bf16.bf16.f32 "
        "{%0,%1,%2,%3}, {%4,%5,%6,%7}, {%8,%9}, {%0,%1,%2,%3};\n"
        : "+f"(c[0]), "+f"(c[1]), "+f"(c[2]), "+f"(c[3])
        : "r"(a[0]), "r"(a[1]), "r"(a[2]), "r"(a[3]), "r"(b[0]), "r"(b[1]));
}

__global__ __launch_bounds__(256, 1)
void k_bgemm(int M, int N, int K,
             const __nv_bfloat16* __restrict__ Ah, const __nv_bfloat16* __restrict__ Al, int lda,
             const __nv_bfloat16* __restrict__ Bh, const __nv_bfloat16* __restrict__ Bl, int ldb,
             float* __restrict__ C, int ldc,
             __nv_bfloat16* __restrict__ Chi, __nv_bfloat16* __restrict__ Clo,
             const float* __restrict__ bias, int mode) {
    __shared__ __align__(16) __nv_bfloat16 sAh[BM * APAD], sAl[BM * APAD];
    __shared__ __align__(16) __nv_bfloat16 sBh[BN * BPAD], sBl[BN * BPAD];

    int tid = threadIdx.x, lane = tid & 31, warp = tid >> 5;
    int wm = (warp & 1) * 64;          // 2 warps along M (64 each)
    int wn = (warp >> 1) * 32;         // 4 warps along N (32 each)
    int m0 = blockIdx.x * BM, n0 = blockIdx.y * BN;

    float acc[4][4][4];
#pragma unroll
    for (int i = 0; i < 4; i++)
#pragma unroll
        for (int j = 0; j < 4; j++)
#pragma unroll
            for (int q = 0; q < 4; q++) acc[i][j][q] = 0.f;

    uint2 rAh[4], rAl[4], rBh[4], rBl[4];

    // prologue: fetch tile 0
#pragma unroll
    for (int l = 0; l < 4; l++) {
        int g = tid + l * 256, row = g >> 3, kk = (g & 7) * 4;
        size_t off = (size_t)(m0 + row) * lda + kk;
        rAh[l] = *(const uint2*)(Ah + off);
        rAl[l] = *(const uint2*)(Al + off);
    }
#pragma unroll
    for (int l = 0; l < 4; l++) {
        int g = tid + l * 256, kk = g >> 5, nb = (g & 31) * 4;
        size_t off = (size_t)kk * ldb + n0 + nb;
        rBh[l] = *(const uint2*)(Bh + off);
        rBl[l] = *(const uint2*)(Bl + off);
    }
    // store tile 0
#pragma unroll
    for (int l = 0; l < 4; l++) {
        int g = tid + l * 256, row = g >> 3, kk = (g & 7) * 4;
        *(uint2*)(sAh + row * APAD + kk) = rAh[l];
        *(uint2*)(sAl + row * APAD + kk) = rAl[l];
    }
#pragma unroll
    for (int l = 0; l < 4; l++) {
        int g = tid + l * 256, kk = g >> 5, nb = (g & 31) * 4;
        __nv_bfloat16 vh[4], vl[4];
        *(uint2*)vh = rBh[l]; *(uint2*)vl = rBl[l];
#pragma unroll
        for (int i = 0; i < 4; i++) {
            sBh[(nb + i) * BPAD + kk] = vh[i];
            sBl[(nb + i) * BPAD + kk] = vl[i];
        }
    }
    __syncthreads();

    for (int k0 = 0; k0 < K; k0 += BK) {
        bool nxt = (k0 + BK) < K;
        if (nxt) {
            int kn = k0 + BK;
#pragma unroll
            for (int l = 0; l < 4; l++) {
                int g = tid + l * 256, row = g >> 3, kk = (g & 7) * 4;
                size_t off = (size_t)(m0 + row) * lda + kn + kk;
                rAh[l] = *(const uint2*)(Ah + off);
                rAl[l] = *(const uint2*)(Al + off);
            }
#pragma unroll
            for (int l = 0; l < 4; l++) {
                int g = tid + l * 256, kk = g >> 5, nb = (g & 31) * 4;
                size_t off = (size_t)(kn + kk) * ldb + n0 + nb;
                rBh[l] = *(const uint2*)(Bh + off);
                rBl[l] = *(const uint2*)(Bl + off);
            }
        }
#pragma unroll
        for (int ks = 0; ks < 2; ks++) {
            int kb = ks * 16;
            uint32_t fah[4][4], fal[4][4];
#pragma unroll
            for (int mt = 0; mt < 4; mt++) {
                int r = wm + mt * 16 + (lane >> 2);
                int cc = kb + (lane & 3) * 2;
                fah[mt][0] = *(const uint32_t*)(sAh + r * APAD + cc);
                fah[mt][1] = *(const uint32_t*)(sAh + (r + 8) * APAD + cc);
                fah[mt][2] = *(const uint32_t*)(sAh + r * APAD + cc + 8);
                fah[mt][3] = *(const uint32_t*)(sAh + (r + 8) * APAD + cc + 8);
                fal[mt][0] = *(const uint32_t*)(sAl + r * APAD + cc);
                fal[mt][1] = *(const uint32_t*)(sAl + (r + 8) * APAD + cc);
                fal[mt][2] = *(const uint32_t*)(sAl + r * APAD + cc + 8);
                fal[mt][3] = *(const uint32_t*)(sAl + (r + 8) * APAD + cc + 8);
            }
            uint32_t fbh[4][2], fbl[4][2];
#pragma unroll
            for (int nt = 0; nt < 4; nt++) {
                int nn = wn + nt * 8 + (lane >> 2);
                int kk2 = kb + (lane & 3) * 2;
                fbh[nt][0] = *(const uint32_t*)(sBh + nn * BPAD + kk2);
                fbh[nt][1] = *(const uint32_t*)(sBh + nn * BPAD + kk2 + 8);
                fbl[nt][0] = *(const uint32_t*)(sBl + nn * BPAD + kk2);
                fbl[nt][1] = *(const uint32_t*)(sBl + nn * BPAD + kk2 + 8);
            }
#pragma unroll
            for (int mt = 0; mt < 4; mt++)
#pragma unroll
                for (int nt = 0; nt < 4; nt++) {
                    mma16816(acc[mt][nt], fah[mt], fbh[nt]);
                    mma16816(acc[mt][nt], fah[mt], fbl[nt]);
                    mma16816(acc[mt][nt], fal[mt], fbh[nt]);
                }
        }
        __syncthreads();
        if (nxt) {
#pragma unroll
            for (int l = 0; l < 4; l++) {
                int g = tid + l * 256, row = g >> 3, kk = (g & 7) * 4;
                *(uint2*)(sAh + row * APAD + kk) = rAh[l];
                *(uint2*)(sAl + row * APAD + kk) = rAl[l];
            }
#pragma unroll
            for (int l = 0; l < 4; l++) {
                int g = tid + l * 256, kk = g >> 5, nb = (g & 31) * 4;
                __nv_bfloat16 vh[4], vl[4];
                *(uint2*)vh = rBh[l]; *(uint2*)vl = rBl[l];
#pragma unroll
                for (int i = 0; i < 4; i++) {
                    sBh[(nb + i) * BPAD + kk] = vh[i];
                    sBl[(nb + i) * BPAD + kk] = vl[i];
                }
            }
            __syncthreads();
        }
    }

    // epilogue
#pragma unroll
    for (int mt = 0; mt < 4; mt++)
#pragma unroll
        for (int nt = 0; nt < 4; nt++) {
            int r0 = m0 + wm + mt * 16 + (lane >> 2);
            int c0 = n0 + wn + nt * 8 + (lane & 3) * 2;
            float* a4 = acc[mt][nt];
            if (mode == 0) {
                *(float2*)(C + (size_t)r0 * ldc + c0)       = make_float2(a4[0], a4[1]);
                *(float2*)(C + (size_t)(r0 + 8) * ldc + c0) = make_float2(a4[2], a4[3]);
            } else {
#pragma unroll
                for (int h = 0; h < 2; h++) {
                    int r = r0 + h * 8;
                    int s = g_sub[r], o = g_obj[r];
                    float v0 = a4[h * 2 + 0] + g_Psub[(size_t)s * HF + c0]
                             + g_Pobj[(size_t)o * HF + c0] + bias[c0];
                    float v1 = a4[h * 2 + 1] + g_Psub[(size_t)s * HF + c0 + 1]
                             + g_Pobj[(size_t)o * HF + c0 + 1] + bias[c0 + 1];
                    v0 = v0 > 0.f ? v0 : 0.f;
                    v1 = v1 > 0.f ? v1 : 0.f;
                    __nv_bfloat16 h0 = __float2bfloat16(v0);
                    __nv_bfloat16 h1 = __float2bfloat16(v1);
                    __nv_bfloat16 l0 = __float2bfloat16(v0 - __bfloat162float(h0));
                    __nv_bfloat16 l1 = __float2bfloat16(v1 - __bfloat162float(h1));
                    __nv_bfloat162 ph; ph.x = h0; ph.y = h1;
                    __nv_bfloat162 pl; pl.x = l0; pl.y = l1;
                    *(__nv_bfloat162*)(Chi + (size_t)r * ldc + c0) = ph;
                    *(__nv_bfloat162*)(Clo + (size_t)r * ldc + c0) = pl;
                }
            }
        }
}

// ---------------- deterministic CSR ----------------
__global__ void k_scan() {
    __shared__ int sh[NOBJ];
    int t = threadIdx.x;
    sh[t] = g_cnt[t];
    __syncthreads();
    for (int d = 1; d < NOBJ; d <<= 1) {
        int v = (t >= d) ? sh[t - d] : 0;
        __syncthreads();
        sh[t] += v;
        __syncthreads();
    }
    g_off[t + 1] = sh[t];
    if (t == 0) g_off[0] = 0;
}

__global__ void k_scatter() {
    int e = blockIdx.x * blockDim.x + threadIdx.x;
    if (e < EN) {
        int s = g_sub[e];
        int pos = g_off[s] + atomicAdd(&g_cur[s], 1);
        g_elist[pos] = e;
    }
}

__global__ void k_sort() {
    int n = blockIdx.x * blockDim.x + threadIdx.x;
    if (n < NOBJ) {
        int b = g_off[n], e2 = g_off[n + 1];
        for (int i = b + 1; i < e2; i++) {
            int v = g_elist[i];
            int j = i - 1;
            while (j >= b && g_elist[j] > v) { g_elist[j + 1] = g_elist[j]; j--; }
            g_elist[j + 1] = v;
        }
    }
}

__global__ void k_final(const float* __restrict__ of,
                        const float* __restrict__ b2,
                        float* __restrict__ out) {
    int n = blockIdx.x;
    int t = threadIdx.x;  // 128
    int b = g_off[n], e2 = g_off[n + 1];
    float a0 = 0, a1 = 0, a2 = 0, a3 = 0;
    for (int j = b; j < e2; j++) {
        const float* r = g_OUT + (size_t)g_elist[j] * DF;
        a0 += r[t];       a1 += r[t + 128];
        a2 += r[t + 256]; a3 += r[t + 384];
    }
    float cnt = (float)(e2 - b);
    float inv = 1.f / (1.f + cnt);
    const float* ofr = of + (size_t)n * DF;
    float* orow = out + (size_t)n * DF;
    orow[t]       = (ofr[t]       + a0 + cnt * b2[t])       * inv;
    orow[t + 128] = (ofr[t + 128] + a1 + cnt * b2[t + 128]) * inv;
    orow[t + 256] = (ofr[t + 256] + a2 + cnt * b2[t + 256]) * inv;
    orow[t + 384] = (ofr[t + 384] + a3 + cnt * b2[t + 384]) * inv;
}

__global__ void k_pairs_f(const void* __restrict__ pairs, float* __restrict__ out) {
    int i = blockIdx.x * blockDim.x + threadIdx.x;
    if (i < EN * 2) {
        long long v = g_is64 ? ((const long long*)pairs)[i]
                             : (long long)((const int*)pairs)[i];
        out[i] = (float)v;
    }
}

// ---------------- launch ----------------
extern "C" void kernel_launch(void* const* d_in, const int* in_sizes, int n_in,
                              void* d_out, int out_size) {
    const float* of    = (const float*)d_in[0];
    const float* bb    = (const float*)d_in[1];
    const void*  pairs = d_in[2];
    const float* W1    = (const float*)d_in[3];
    const float* b1    = (const float*)d_in[4];
    const float* W2    = (const float*)d_in[5];
    const float* b2    = (const float*)d_in[6];
    float* out = (float*)d_out;
    cudaStream_t s = 0;

    float *pPsub, *pPobj, *pOUT;
    __nv_bfloat16 *pOFh, *pOFl, *pW1h, *pW1l, *pW2h, *pW2l, *pBGh, *pBGl, *pHh, *pHl;
    cudaGetSymbolAddress((void**)&pPsub, g_Psub);
    cudaGetSymbolAddress((void**)&pPobj, g_Pobj);
    cudaGetSymbolAddress((void**)&pOUT,  g_OUT);
    cudaGetSymbolAddress((void**)&pOFh,  g_OFh);
    cudaGetSymbolAddress((void**)&pOFl,  g_OFl);
    cudaGetSymbolAddress((void**)&pW1h,  g_W1h);
    cudaGetSymbolAddress((void**)&pW1l,  g_W1l);
    cudaGetSymbolAddress((void**)&pW2h,  g_W2h);
    cudaGetSymbolAddress((void**)&pW2l,  g_W2l);
    cudaGetSymbolAddress((void**)&pBGh,  g_bbGh);
    cudaGetSymbolAddress((void**)&pBGl,  g_bbGl);
    cudaGetSymbolAddress((void**)&pHh,   g_Hh);
    cudaGetSymbolAddress((void**)&pHl,   g_Hl);

    k_detect<<<1, 32, 0, s>>>((const int*)pairs);
    k_zero<<<(NOBJ + 255) / 256, 256, 0, s>>>();
    k_prep<<<EN / 256, 256, 0, s>>>(pairs);
    k_gather<<<(EN * DBF) / 256, 256, 0, s>>>(bb);

    k_split<<<(NOBJ * DF + 255) / 256, 256, 0, s>>>(of, pOFh, pOFl, NOBJ * DF);
    k_split<<<(W1R * HF + 255) / 256, 256, 0, s>>>(W1, pW1h, pW1l, W1R * HF);
    k_split<<<(HF * DF + 255) / 256, 256, 0, s>>>(W2, pW2h, pW2l, HF * DF);

    // Psub = OF @ W1[0:512,:]   Pobj = OF @ W1[512:1024,:]
    k_bgemm<<<dim3(NOBJ / BM, HF / BN), 256, 0, s>>>(
        NOBJ, HF, DF, pOFh, pOFl, DF, pW1h, pW1l, HF,
        pPsub, HF, nullptr, nullptr, nullptr, 0);
    k_bgemm<<<dim3(NOBJ / BM, HF / BN), 256, 0, s>>>(
        NOBJ, HF, DF, pOFh, pOFl, DF, pW1h + (size_t)512 * HF, pW1l + (size_t)512 * HF, HF,
        pPobj, HF, nullptr, nullptr, nullptr, 0);

    // H = relu(bbG @ W1[1024:1088,:] + Psub[sub] + Pobj[obj] + b1)  -> (Hh,Hl) bf16
    k_bgemm<<<dim3(EN / BM, HF / BN), 256, 0, s>>>(
        EN, HF, DBF, pBGh, pBGl, DBF, pW1h + (size_t)1024 * HF, pW1l + (size_t)1024 * HF, HF,
        nullptr, HF, pHh, pHl, b1, 1);

    // OUT = H @ W2
    k_bgemm<<<dim3(EN / BM, DF / BN), 256, 0, s>>>(
        EN, DF, HF, pHh, pHl, HF, pW2h, pW2l, DF,
        pOUT, DF, nullptr, nullptr, nullptr, 0);

    // deterministic segment sum
    k_scan<<<1, NOBJ, 0, s>>>();
    k_scatter<<<EN / 256, 256, 0, s>>>();
    k_sort<<<(NOBJ + 255) / 256, 256, 0, s>>>();
    k_final<<<NOBJ, 128, 0, s>>>(of, b2, out);

    // output assembly: new_feats | bboxes_embedding | pairs (layout per out_size)
    const long long NEWF = (long long)NOBJ * DF;             // 524288
    const long long BBn  = (long long)NOBJ * NOBJ * DBF;     // 67108864
    long long osz = (long long)out_size;
    if (osz >= NEWF + BBn) {
        cudaMemcpyAsync(out + NEWF, bb, (size_t)BBn * sizeof(float),
                        cudaMemcpyDeviceToDevice, s);
        long long rem = osz - NEWF - BBn;
        if (rem == (long long)EN * 2) {
            k_pairs_f<<<(EN * 2) / 256, 256, 0, s>>>(pairs, out + NEWF + BBn);
        } else if (rem == (long long)EN * 4) {
            cudaMemcpyAsync(out + NEWF + BBn, pairs,
                            (size_t)EN * 2 * sizeof(long long),
                            cudaMemcpyDeviceToDevice, s);
        }
    }
}